// round 12
// baseline (speedup 1.0000x reference)
#include <cuda_runtime.h>
#include <cuda_bf16.h>
#include <math_constants.h>

#define D        128
#define NODES_MX 40000
#define EDGES_MX 640000
#define SCALE_INV 0.08838834764831845f   // 1/sqrt(128)

// ---------------- scratch (device globals) ----------------
__device__ float g_mperm[EDGES_MX * D];  // messages permuted into CSR order
__device__ float g_summed[NODES_MX * D];
__device__ float g_qk[NODES_MX * D];
__device__ float g_wm[NODES_MX * D];
__device__ float g_qb[NODES_MX];
__device__ float g_sums[NODES_MX];
__device__ float g_att[EDGES_MX];
__device__ int   g_counts[NODES_MX];
__device__ int   g_offsets[NODES_MX + 1];
__device__ int   g_cursor[NODES_MX];
__device__ int   g_eids[EDGES_MX];
__device__ int   g_bsum[512];
__device__ float g_Wqk[D * D];   // Wq @ Wk^T
__device__ float g_Wvo[D * D];   // Wv @ Wo
__device__ float g_bqk[D];       // bq @ Wk^T
__device__ float g_wqb[D];       // Wq @ bk
__device__ float g_bvo[D];       // bv @ Wo
__device__ float g_bqb[1];       // bq . bk

// ---------------- f32x2 helpers (GEMMs only) ----------------
__device__ __forceinline__ unsigned long long ffma2(unsigned long long a,
                                                    unsigned long long b,
                                                    unsigned long long c) {
    unsigned long long d;
    asm("fma.rn.f32x2 %0, %1, %2, %3;" : "=l"(d) : "l"(a), "l"(b), "l"(c));
    return d;
}
__device__ __forceinline__ unsigned long long pk2(float lo, float hi) {
    unsigned long long r;
    asm("mov.b64 %0, {%1, %2};" : "=l"(r) : "f"(lo), "f"(hi));
    return r;
}
__device__ __forceinline__ float2 upk2(unsigned long long v) {
    float lo, hi;
    asm("mov.b64 {%0, %1}, %2;" : "=f"(lo), "=f"(hi) : "l"(v));
    return make_float2(lo, hi);
}

// ---------------- init ----------------
__global__ void k_init(int N) {
    int i = blockIdx.x * blockDim.x + threadIdx.x;
    if (i < N) g_counts[i] = 0;
}

// ---------------- precompute fused weights ----------------
__global__ void k_pre(const float* __restrict__ Wk, const float* __restrict__ bk,
                      const float* __restrict__ Wv, const float* __restrict__ bv,
                      const float* __restrict__ Wq, const float* __restrict__ bq,
                      const float* __restrict__ Wo) {
    int i = blockIdx.x;     // 0..127
    int j = threadIdx.x;    // 0..127
    float a = 0.f, c = 0.f;
#pragma unroll 8
    for (int t = 0; t < D; t++) {
        a = fmaf(Wq[i * D + t], Wk[j * D + t], a);   // (Wq Wk^T)[i][j]
        c = fmaf(Wv[i * D + t], Wo[t * D + j], c);   // (Wv Wo)[i][j]
    }
    g_Wqk[i * D + j] = a;
    g_Wvo[i * D + j] = c;
    if (i == 0) {
        float b1 = 0.f, b2 = 0.f, b3 = 0.f;
#pragma unroll 8
        for (int t = 0; t < D; t++) {
            b1 = fmaf(bq[t], Wk[j * D + t], b1);     // (bq Wk^T)[j]
            b2 = fmaf(Wq[j * D + t], bk[t], b2);     // (Wq bk)[j]
            b3 = fmaf(bv[t], Wo[t * D + j], b3);     // (bv Wo)[j]
        }
        g_bqk[j] = b1; g_wqb[j] = b2; g_bvo[j] = b3;
        if (j == 0) {
            float b = 0.f;
            for (int t = 0; t < D; t++) b = fmaf(bq[t], bk[t], b);
            g_bqb[0] = b;
        }
    }
}

// ---------------- CSR build ----------------
__global__ void k_hist(const int* __restrict__ recv, int E) {
    for (int e = blockIdx.x * blockDim.x + threadIdx.x; e < E; e += gridDim.x * blockDim.x)
        atomicAdd(&g_counts[recv[e]], 1);
}

__global__ void k_scan1(int N) {
    int i = blockIdx.x * 256 + threadIdx.x;
    int v = (i < N) ? g_counts[i] : 0;
    int lane = threadIdx.x & 31, wid = threadIdx.x >> 5;
#pragma unroll
    for (int off = 16; off > 0; off >>= 1) v += __shfl_xor_sync(0xffffffffu, v, off);
    __shared__ int ws[8];
    if (lane == 0) ws[wid] = v;
    __syncthreads();
    if (threadIdx.x == 0) {
        int s = 0;
#pragma unroll
        for (int w = 0; w < 8; w++) s += ws[w];
        g_bsum[blockIdx.x] = s;
    }
}

__global__ void k_scan2(int nb) {
    int tid = threadIdx.x;
    int v = (tid < nb) ? g_bsum[tid] : 0;
    int lane = tid & 31, wid = tid >> 5;
    int x = v;
#pragma unroll
    for (int off = 1; off < 32; off <<= 1) {
        int t = __shfl_up_sync(0xffffffffu, x, off);
        if (lane >= off) x += t;
    }
    __shared__ int ws[8];
    if (lane == 31) ws[wid] = x;
    __syncthreads();
    if (wid == 0) {
        int t = (lane < 8) ? ws[lane] : 0;
#pragma unroll
        for (int off = 1; off < 8; off <<= 1) {
            int u = __shfl_up_sync(0xffffffffu, t, off);
            if (lane >= off) t += u;
        }
        if (lane < 8) ws[lane] = t;
    }
    __syncthreads();
    int incl = x + (wid ? ws[wid - 1] : 0);
    if (tid < nb) g_bsum[tid] = incl - v;   // exclusive
}

__global__ void k_scan3(int N, int E) {
    int i = blockIdx.x * 256 + threadIdx.x;
    int v = (i < N) ? g_counts[i] : 0;
    int lane = threadIdx.x & 31, wid = threadIdx.x >> 5;
    int x = v;
#pragma unroll
    for (int off = 1; off < 32; off <<= 1) {
        int t = __shfl_up_sync(0xffffffffu, x, off);
        if (lane >= off) x += t;
    }
    __shared__ int ws[8];
    if (lane == 31) ws[wid] = x;
    __syncthreads();
    if (wid == 0) {
        int t = (lane < 8) ? ws[lane] : 0;
#pragma unroll
        for (int off = 1; off < 8; off <<= 1) {
            int u = __shfl_up_sync(0xffffffffu, t, off);
            if (lane >= off) t += u;
        }
        if (lane < 8) ws[lane] = t;
    }
    __syncthreads();
    int excl = x - v + (wid ? ws[wid - 1] : 0) + g_bsum[blockIdx.x];
    if (i < N) { g_offsets[i] = excl; g_cursor[i] = excl; }
    if (i == 0) g_offsets[N] = E;
}

__global__ void k_scatter(const int* __restrict__ recv, int E) {
    for (int e = blockIdx.x * blockDim.x + threadIdx.x; e < E; e += gridDim.x * blockDim.x) {
        int pos = atomicAdd(&g_cursor[recv[e]], 1);
        g_eids[pos] = e;
    }
}

// ------- pass 1: summed[n] = sum of node's messages; also permute rows into g_mperm ----
__global__ void __launch_bounds__(256) k_sum_nodes(const float* __restrict__ messages, int N) {
    int gw = (blockIdx.x * blockDim.x + threadIdx.x) >> 5;
    int lane = threadIdx.x & 31;
    if (gw >= N) return;
    int beg = g_offsets[gw], deg = g_offsets[gw + 1] - beg;
    const float4* m4 = (const float4*)messages;
    float4* p4 = (float4*)g_mperm;
    float4 acc = make_float4(0.f, 0.f, 0.f, 0.f);
    for (int k0 = 0; k0 < deg; k0 += 8) {
        int kb = deg - k0; if (kb > 8) kb = 8;
        int ee[8]; float4 mm[8];
#pragma unroll
        for (int j = 0; j < 8; j++) if (j < kb) ee[j] = __ldg(&g_eids[beg + k0 + j]);
#pragma unroll
        for (int j = 0; j < 8; j++) if (j < kb) mm[j] = __ldg(m4 + (size_t)ee[j] * 32 + lane);
#pragma unroll
        for (int j = 0; j < 8; j++) if (j < kb) {
            acc.x += mm[j].x; acc.y += mm[j].y; acc.z += mm[j].z; acc.w += mm[j].w;
            p4[(size_t)(beg + k0 + j) * 32 + lane] = mm[j];
        }
    }
    ((float4*)g_summed)[(size_t)gw * 32 + lane] = acc;
}

// ---------------- node projection (f32x2, TN=32): qk = summed @ Wqk + bqk ; qb ---------
__global__ void __launch_bounds__(128) k_qkproj(int N) {
    const int TN = 32, P = 16;
    __shared__ __align__(16) float2 sp[P][D];
    int n0 = blockIdx.x * TN;
    int j = threadIdx.x;   // 0..127
#pragma unroll
    for (int p = 0; p < P; p++) {
        int na = n0 + 2 * p, nb = n0 + 2 * p + 1;
        if (na >= N) na = N - 1;
        if (nb >= N) nb = N - 1;
        sp[p][j] = make_float2(g_summed[(size_t)na * D + j], g_summed[(size_t)nb * D + j]);
    }
    __syncthreads();
    float bj = g_bqk[j];
    unsigned long long acc[P];
#pragma unroll
    for (int p = 0; p < P; p++) acc[p] = pk2(bj, bj);
#pragma unroll 4
    for (int i = 0; i < D; i++) {
        float w = __ldg(&g_Wqk[i * D + j]);
        unsigned long long bb = pk2(w, w);
#pragma unroll
        for (int p = 0; p < P; p++) {
            unsigned long long aa = *(const unsigned long long*)&sp[p][i];
            acc[p] = ffma2(aa, bb, acc[p]);
        }
    }
#pragma unroll
    for (int p = 0; p < P; p++) {
        float2 r = upk2(acc[p]);
        int na = n0 + 2 * p, nb = n0 + 2 * p + 1;
        if (na < N) g_qk[(size_t)na * D + j] = r.x;
        if (nb < N) g_qk[(size_t)nb * D + j] = r.y;
    }
    if (j < TN) {
        int n = n0 + j;
        if (n < N) {
            float a = g_bqb[0];
            for (int i = 0; i < D; i++) {
                float2 v = sp[j >> 1][i];
                a = fmaf((j & 1) ? v.y : v.x, g_wqb[i], a);
            }
            g_qb[n] = a;
        }
    }
}

// ------ pass 2: scores from sequential g_mperm + warp softmax -> normalized weights ----
__global__ void __launch_bounds__(256) k_score(int N) {
    int gw = (blockIdx.x * blockDim.x + threadIdx.x) >> 5;
    int lane = threadIdx.x & 31;
    if (gw >= N) return;
    int beg = g_offsets[gw], deg = g_offsets[gw + 1] - beg;
    if (deg == 0) { if (lane == 0) g_sums[gw] = 0.f; return; }
    const float4* m4 = (const float4*)g_mperm;
    float4 q = __ldg((const float4*)g_qk + (size_t)gw * 32 + lane);
    float qb = __ldg(&g_qb[gw]);

    float myscore = -CUDART_INF_F;
    int kmain = deg < 32 ? deg : 32;
    for (int k0 = 0; k0 < kmain; k0 += 8) {
        int kb = kmain - k0; if (kb > 8) kb = 8;
        float4 mm[8]; float s[8];
#pragma unroll
        for (int j = 0; j < 8; j++) if (j < kb)
            mm[j] = m4[(size_t)(beg + k0 + j) * 32 + lane];
#pragma unroll
        for (int j = 0; j < 8; j++) if (j < kb)
            s[j] = mm[j].x * q.x + mm[j].y * q.y + mm[j].z * q.z + mm[j].w * q.w;
#pragma unroll
        for (int off = 16; off > 0; off >>= 1) {
#pragma unroll
            for (int j = 0; j < 8; j++) if (j < kb)
                s[j] += __shfl_xor_sync(0xffffffffu, s[j], off);
        }
#pragma unroll
        for (int j = 0; j < 8; j++) if (j < kb)
            if (lane == k0 + j) myscore = (s[j] + qb) * SCALE_INV;
    }
    // rare tail: deg > 32 -> raw scores to global
    float tailmax = -CUDART_INF_F;
    for (int k = 32; k < deg; k++) {
        float4 m = m4[(size_t)(beg + k) * 32 + lane];
        float d = m.x * q.x + m.y * q.y + m.z * q.z + m.w * q.w;
#pragma unroll
        for (int off = 16; off > 0; off >>= 1)
            d += __shfl_xor_sync(0xffffffffu, d, off);
        float s = (d + qb) * SCALE_INV;
        if (lane == 0) g_att[beg + k] = s;
        tailmax = fmaxf(tailmax, s);
    }
    // softmax
    float mx = myscore;
#pragma unroll
    for (int off = 16; off > 0; off >>= 1)
        mx = fmaxf(mx, __shfl_xor_sync(0xffffffffu, mx, off));
    mx = fmaxf(mx, tailmax);
    float ex = (lane < kmain) ? __expf(myscore - mx) : 0.f;
    float p = ex;
#pragma unroll
    for (int off = 16; off > 0; off >>= 1)
        p += __shfl_xor_sync(0xffffffffu, p, off);
    if (deg > 32) {
        float pt = 0.f;
        for (int k = 32 + lane; k < deg; k += 32) pt += __expf(g_att[beg + k] - mx);
#pragma unroll
        for (int off = 16; off > 0; off >>= 1)
            pt += __shfl_xor_sync(0xffffffffu, pt, off);
        p += pt;
    }
    float inv = 1.f / (p + 1e-8f);
    if (lane == 0) g_sums[gw] = p;
    if (lane < kmain) g_att[beg + lane] = ex * inv;
    if (deg > 32)
        for (int k = 32 + lane; k < deg; k += 32)
            g_att[beg + k] = __expf(g_att[beg + k] - mx) * inv;
}

// ---------------- pass 3: weighted aggregation from sequential g_mperm ----------------
__global__ void __launch_bounds__(256) k_agg(int N) {
    int gw = (blockIdx.x * blockDim.x + threadIdx.x) >> 5;
    int lane = threadIdx.x & 31;
    if (gw >= N) return;
    int beg = g_offsets[gw], deg = g_offsets[gw + 1] - beg;
    const float4* m4 = (const float4*)g_mperm;
    float myatt = (lane < deg) ? __ldg(&g_att[beg + lane]) : 0.f;
    float4 acc = make_float4(0.f, 0.f, 0.f, 0.f);
    for (int k0 = 0; k0 < deg; k0 += 8) {
        int kb = deg - k0; if (kb > 8) kb = 8;
        float4 mm[8]; float ww[8];
#pragma unroll
        for (int j = 0; j < 8; j++) if (j < kb) {
            int k = k0 + j;
            ww[j] = (k < 32) ? __shfl_sync(0xffffffffu, myatt, k)
                             : __ldg(&g_att[beg + k]);
            mm[j] = m4[(size_t)(beg + k) * 32 + lane];
        }
#pragma unroll
        for (int j = 0; j < 8; j++) if (j < kb) {
            acc.x = fmaf(ww[j], mm[j].x, acc.x);
            acc.y = fmaf(ww[j], mm[j].y, acc.y);
            acc.z = fmaf(ww[j], mm[j].z, acc.z);
            acc.w = fmaf(ww[j], mm[j].w, acc.w);
        }
    }
    ((float4*)g_wm)[(size_t)gw * 32 + lane] = acc;
}

// ---------------- output projection (f32x2, TN=32): out = wm @ Wvo + asum*bvo + bo ----
__global__ void __launch_bounds__(128) k_out(const float* __restrict__ bo,
                                             float* __restrict__ out, int N) {
    const int TN = 32, P = 16;
    __shared__ __align__(16) float2 sp[P][D];
    __shared__ float sas[TN];
    int n0 = blockIdx.x * TN;
    int j = threadIdx.x;
#pragma unroll
    for (int p = 0; p < P; p++) {
        int na = n0 + 2 * p, nb = n0 + 2 * p + 1;
        if (na >= N) na = N - 1;
        if (nb >= N) nb = N - 1;
        sp[p][j] = make_float2(g_wm[(size_t)na * D + j], g_wm[(size_t)nb * D + j]);
    }
    if (j < TN) {
        int n = n0 + j; if (n >= N) n = N - 1;
        float s = g_sums[n];
        sas[j] = s / (s + 1e-8f);
    }
    __syncthreads();
    float bvoj = g_bvo[j];
    float boj  = __ldg(bo + j);
    unsigned long long acc[P];
#pragma unroll
    for (int p = 0; p < P; p++)
        acc[p] = pk2(fmaf(sas[2 * p], bvoj, boj), fmaf(sas[2 * p + 1], bvoj, boj));
#pragma unroll 4
    for (int i = 0; i < D; i++) {
        float w = __ldg(&g_Wvo[i * D + j]);
        unsigned long long bb = pk2(w, w);
#pragma unroll
        for (int p = 0; p < P; p++) {
            unsigned long long aa = *(const unsigned long long*)&sp[p][i];
            acc[p] = ffma2(aa, bb, acc[p]);
        }
    }
#pragma unroll
    for (int p = 0; p < P; p++) {
        float2 r = upk2(acc[p]);
        int na = n0 + 2 * p, nb = n0 + 2 * p + 1;
        if (na < N) out[(size_t)na * D + j] = r.x;
        if (nb < N) out[(size_t)nb * D + j] = r.y;
    }
}

// ---------------- launch ----------------
extern "C" void kernel_launch(void* const* d_in, const int* in_sizes, int n_in,
                              void* d_out, int out_size) {
    const float* messages = (const float*)d_in[0];
    const int*   recv     = (const int*)d_in[1];
    int wb = (n_in >= 11) ? 3 : 2;
    const float* Wk = (const float*)d_in[wb + 0];
    const float* bk = (const float*)d_in[wb + 1];
    const float* Wv = (const float*)d_in[wb + 2];
    const float* bv = (const float*)d_in[wb + 3];
    const float* Wq = (const float*)d_in[wb + 4];
    const float* bq = (const float*)d_in[wb + 5];
    const float* Wo = (const float*)d_in[wb + 6];
    const float* bo = (const float*)d_in[wb + 7];
    float* out = (float*)d_out;

    int E = in_sizes[0] / D;
    int N = out_size / D;
    int nb = (N + 255) / 256;

    k_init<<<(N + 255) / 256, 256>>>(N);
    k_pre<<<D, D>>>(Wk, bk, Wv, bv, Wq, bq, Wo);
    k_hist<<<(E + 255) / 256, 256>>>(recv, E);
    k_scan1<<<nb, 256>>>(N);
    k_scan2<<<1, 256>>>(nb);
    k_scan3<<<nb, 256>>>(N, E);
    k_scatter<<<(E + 255) / 256, 256>>>(recv, E);
    k_sum_nodes<<<(N + 7) / 8, 256>>>(messages, N);
    k_qkproj<<<(N + 31) / 32, 128>>>(N);
    k_score<<<(N + 7) / 8, 256>>>(N);
    k_agg<<<(N + 7) / 8, 256>>>(N);
    k_out<<<(N + 31) / 32, 128>>>(bo, out, N);
}

// round 16
// speedup vs baseline: 1.2313x; 1.2313x over previous
#include <cuda_runtime.h>
#include <cuda_bf16.h>
#include <math_constants.h>

#define D        128
#define NODES_MX 40000
#define EDGES_MX 640000
#define SCALE_INV 0.08838834764831845f   // 1/sqrt(128)

// ---------------- scratch (device globals) ----------------
__device__ float g_summed[NODES_MX * D];
__device__ float g_qk[NODES_MX * D];
__device__ float g_wm[NODES_MX * D];
__device__ float g_qb[NODES_MX];
__device__ float g_sums[NODES_MX];
__device__ float g_scores[EDGES_MX];   // raw scores for deg>32 tail
__device__ float g_att[EDGES_MX];      // normalized attention weights
__device__ int   g_counts[NODES_MX];
__device__ int   g_offsets[NODES_MX + 1];
__device__ int   g_cursor[NODES_MX];
__device__ int   g_eids[EDGES_MX];
__device__ int   g_bsum[512];
__device__ float g_Wqk[D * D];   // Wq @ Wk^T
__device__ float g_Wvo[D * D];   // Wv @ Wo
__device__ float g_bqk[D];       // bq @ Wk^T
__device__ float g_wqb[D];       // Wq @ bk
__device__ float g_bvo[D];       // bv @ Wo
__device__ float g_bqb[1];       // bq . bk

// ---------------- f32x2 helpers (GEMMs only) ----------------
__device__ __forceinline__ unsigned long long ffma2(unsigned long long a,
                                                    unsigned long long b,
                                                    unsigned long long c) {
    unsigned long long d;
    asm("fma.rn.f32x2 %0, %1, %2, %3;" : "=l"(d) : "l"(a), "l"(b), "l"(c));
    return d;
}
__device__ __forceinline__ unsigned long long pk2(float lo, float hi) {
    unsigned long long r;
    asm("mov.b64 %0, {%1, %2};" : "=l"(r) : "f"(lo), "f"(hi));
    return r;
}
__device__ __forceinline__ float2 upk2(unsigned long long v) {
    float lo, hi;
    asm("mov.b64 {%0, %1}, %2;" : "=f"(lo), "=f"(hi) : "l"(v));
    return make_float2(lo, hi);
}

// ---------------- init ----------------
__global__ void k_init(int N) {
    int i = blockIdx.x * blockDim.x + threadIdx.x;
    if (i < N) g_counts[i] = 0;
}

// ---------------- precompute fused weights ----------------
__global__ void k_pre(const float* __restrict__ Wk, const float* __restrict__ bk,
                      const float* __restrict__ Wv, const float* __restrict__ bv,
                      const float* __restrict__ Wq, const float* __restrict__ bq,
                      const float* __restrict__ Wo) {
    int i = blockIdx.x;     // 0..127
    int j = threadIdx.x;    // 0..127
    float a = 0.f, c = 0.f;
#pragma unroll 8
    for (int t = 0; t < D; t++) {
        a = fmaf(Wq[i * D + t], Wk[j * D + t], a);   // (Wq Wk^T)[i][j]
        c = fmaf(Wv[i * D + t], Wo[t * D + j], c);   // (Wv Wo)[i][j]
    }
    g_Wqk[i * D + j] = a;
    g_Wvo[i * D + j] = c;
    if (i == 0) {
        float b1 = 0.f, b2 = 0.f, b3 = 0.f;
#pragma unroll 8
        for (int t = 0; t < D; t++) {
            b1 = fmaf(bq[t], Wk[j * D + t], b1);     // (bq Wk^T)[j]
            b2 = fmaf(Wq[j * D + t], bk[t], b2);     // (Wq bk)[j]
            b3 = fmaf(bv[t], Wo[t * D + j], b3);     // (bv Wo)[j]
        }
        g_bqk[j] = b1; g_wqb[j] = b2; g_bvo[j] = b3;
        if (j == 0) {
            float b = 0.f;
            for (int t = 0; t < D; t++) b = fmaf(bq[t], bk[t], b);
            g_bqb[0] = b;
        }
    }
}

// ---------------- CSR build ----------------
__global__ void k_hist(const int* __restrict__ recv, int E) {
    for (int e = blockIdx.x * blockDim.x + threadIdx.x; e < E; e += gridDim.x * blockDim.x)
        atomicAdd(&g_counts[recv[e]], 1);
}

__global__ void k_scan1(int N) {
    int i = blockIdx.x * 256 + threadIdx.x;
    int v = (i < N) ? g_counts[i] : 0;
    int lane = threadIdx.x & 31, wid = threadIdx.x >> 5;
#pragma unroll
    for (int off = 16; off > 0; off >>= 1) v += __shfl_xor_sync(0xffffffffu, v, off);
    __shared__ int ws[8];
    if (lane == 0) ws[wid] = v;
    __syncthreads();
    if (threadIdx.x == 0) {
        int s = 0;
#pragma unroll
        for (int w = 0; w < 8; w++) s += ws[w];
        g_bsum[blockIdx.x] = s;
    }
}

// merged scan2+scan3: each block redundantly reduces g_bsum[0..blockIdx) for its carry
__global__ void k_scan23(int N, int E, int nb) {
    int tid = threadIdx.x;
    int lane = tid & 31, wid = tid >> 5;
    __shared__ int ws[8];
    // carry = sum of g_bsum[0..blockIdx.x)
    int cv = (tid < blockIdx.x && tid < nb) ? g_bsum[tid] : 0;
#pragma unroll
    for (int off = 16; off > 0; off >>= 1) cv += __shfl_xor_sync(0xffffffffu, cv, off);
    if (lane == 0) ws[wid] = cv;
    __syncthreads();
    int carry = 0;
    {
        int t = (lane < 8) ? ws[lane] : 0;
#pragma unroll
        for (int off = 4; off > 0; off >>= 1) t += __shfl_xor_sync(0xffffffffu, t, off);
        carry = __shfl_sync(0xffffffffu, t, 0);
    }
    __syncthreads();
    // block-local exclusive scan of counts
    int i = blockIdx.x * 256 + tid;
    int v = (i < N) ? g_counts[i] : 0;
    int x = v;
#pragma unroll
    for (int off = 1; off < 32; off <<= 1) {
        int t = __shfl_up_sync(0xffffffffu, x, off);
        if (lane >= off) x += t;
    }
    if (lane == 31) ws[wid] = x;
    __syncthreads();
    if (wid == 0) {
        int t = (lane < 8) ? ws[lane] : 0;
#pragma unroll
        for (int off = 1; off < 8; off <<= 1) {
            int u = __shfl_up_sync(0xffffffffu, t, off);
            if (lane >= off) t += u;
        }
        if (lane < 8) ws[lane] = t;
    }
    __syncthreads();
    int excl = x - v + (wid ? ws[wid - 1] : 0) + carry;
    if (i < N) { g_offsets[i] = excl; g_cursor[i] = excl; }
    if (i == 0) g_offsets[N] = E;
}

__global__ void k_scatter(const int* __restrict__ recv, int E) {
    for (int e = blockIdx.x * blockDim.x + threadIdx.x; e < E; e += gridDim.x * blockDim.x) {
        int pos = atomicAdd(&g_cursor[recv[e]], 1);
        g_eids[pos] = e;
    }
}

// ---------------- pass 1: summed[n] = sum of messages over node's edges ----------------
__global__ void __launch_bounds__(256) k_sum_nodes(const float* __restrict__ messages, int N) {
    int gw = (blockIdx.x * blockDim.x + threadIdx.x) >> 5;
    int lane = threadIdx.x & 31;
    if (gw >= N) return;
    int beg = g_offsets[gw], deg = g_offsets[gw + 1] - beg;
    const float4* m4 = (const float4*)messages;
    float4 acc = make_float4(0.f, 0.f, 0.f, 0.f);
    for (int k0 = 0; k0 < deg; k0 += 8) {
        int kb = deg - k0; if (kb > 8) kb = 8;
        int ee[8]; float4 mm[8];
#pragma unroll
        for (int j = 0; j < 8; j++) if (j < kb) ee[j] = __ldg(&g_eids[beg + k0 + j]);
#pragma unroll
        for (int j = 0; j < 8; j++) if (j < kb) mm[j] = __ldg(m4 + (size_t)ee[j] * 32 + lane);
#pragma unroll
        for (int j = 0; j < 8; j++) if (j < kb) {
            acc.x += mm[j].x; acc.y += mm[j].y; acc.z += mm[j].z; acc.w += mm[j].w;
        }
    }
    ((float4*)g_summed)[(size_t)gw * 32 + lane] = acc;
}

// ---------------- node projection: qk = summed @ Wqk + bqk ; qb (R3 verbatim) ----------
__global__ void __launch_bounds__(128) k_qkproj(int N) {
    const int TN = 16, P = 8;
    __shared__ __align__(16) float2 sp[P][D];
    int n0 = blockIdx.x * TN;
    int j = threadIdx.x;   // 0..127
#pragma unroll
    for (int p = 0; p < P; p++) {
        int na = n0 + 2 * p, nb = n0 + 2 * p + 1;
        if (na >= N) na = N - 1;
        if (nb >= N) nb = N - 1;
        sp[p][j] = make_float2(g_summed[(size_t)na * D + j], g_summed[(size_t)nb * D + j]);
    }
    __syncthreads();
    float bj = g_bqk[j];
    unsigned long long acc[P];
#pragma unroll
    for (int p = 0; p < P; p++) acc[p] = pk2(bj, bj);
#pragma unroll 4
    for (int i = 0; i < D; i++) {
        float w = __ldg(&g_Wqk[i * D + j]);
        unsigned long long bb = pk2(w, w);
#pragma unroll
        for (int p = 0; p < P; p++) {
            unsigned long long aa = *(const unsigned long long*)&sp[p][i];
            acc[p] = ffma2(aa, bb, acc[p]);
        }
    }
#pragma unroll
    for (int p = 0; p < P; p++) {
        float2 r = upk2(acc[p]);
        int na = n0 + 2 * p, nb = n0 + 2 * p + 1;
        if (na < N) g_qk[(size_t)na * D + j] = r.x;
        if (nb < N) g_qk[(size_t)nb * D + j] = r.y;
    }
    if (j < TN) {
        int n = n0 + j;
        if (n < N) {
            float a = g_bqb[0];
            for (int i = 0; i < D; i++) {
                float2 v = sp[j >> 1][i];
                a = fmaf((j & 1) ? v.y : v.x, g_wqb[i], a);
            }
            g_qb[n] = a;
        }
    }
}

// -------- pass 2 (chunked): scores + warp softmax -> normalized weights (R3 body) ------
__global__ void __launch_bounds__(256) k_score(const float* __restrict__ messages,
                                               int n0, int n1) {
    int gw = n0 + ((blockIdx.x * blockDim.x + threadIdx.x) >> 5);
    int lane = threadIdx.x & 31;
    if (gw >= n1) return;
    int beg = g_offsets[gw], deg = g_offsets[gw + 1] - beg;
    if (deg == 0) { if (lane == 0) g_sums[gw] = 0.f; return; }
    const float4* m4 = (const float4*)messages;
    float4 q = __ldg((const float4*)g_qk + (size_t)gw * 32 + lane);
    float qb = __ldg(&g_qb[gw]);
    float myscore = -CUDART_INF_F;
    int kmain = deg < 32 ? deg : 32;
    for (int k0 = 0; k0 < kmain; k0 += 8) {
        int kb = kmain - k0; if (kb > 8) kb = 8;
        int ee[8]; float4 mm[8];
#pragma unroll
        for (int j = 0; j < 8; j++) if (j < kb) ee[j] = __ldg(&g_eids[beg + k0 + j]);
#pragma unroll
        for (int j = 0; j < 8; j++) if (j < kb) mm[j] = __ldg(m4 + (size_t)ee[j] * 32 + lane);
#pragma unroll
        for (int j = 0; j < 8; j++) if (j < kb) {
            float d = mm[j].x * q.x + mm[j].y * q.y + mm[j].z * q.z + mm[j].w * q.w;
#pragma unroll
            for (int off = 16; off > 0; off >>= 1)
                d += __shfl_xor_sync(0xffffffffu, d, off);
            float s = (d + qb) * SCALE_INV;
            if (lane == k0 + j) myscore = s;
        }
    }
    // rare tail: deg > 32
    float tailmax = -CUDART_INF_F;
    for (int k = 32; k < deg; k++) {
        int e = __ldg(&g_eids[beg + k]);
        float4 m = __ldg(m4 + (size_t)e * 32 + lane);
        float d = m.x * q.x + m.y * q.y + m.z * q.z + m.w * q.w;
#pragma unroll
        for (int off = 16; off > 0; off >>= 1)
            d += __shfl_xor_sync(0xffffffffu, d, off);
        float s = (d + qb) * SCALE_INV;
        if (lane == 0) g_scores[beg + k] = s;
        tailmax = fmaxf(tailmax, s);
    }
    float mx = myscore;
#pragma unroll
    for (int off = 16; off > 0; off >>= 1)
        mx = fmaxf(mx, __shfl_xor_sync(0xffffffffu, mx, off));
    mx = fmaxf(mx, tailmax);
    float ex = (lane < kmain) ? __expf(myscore - mx) : 0.f;
    float p = ex;
#pragma unroll
    for (int off = 16; off > 0; off >>= 1)
        p += __shfl_xor_sync(0xffffffffu, p, off);
    float ptail = 0.f;
    for (int k = 32 + lane; k < deg; k += 32) ptail += __expf(g_scores[beg + k] - mx);
#pragma unroll
    for (int off = 16; off > 0; off >>= 1)
        ptail += __shfl_xor_sync(0xffffffffu, ptail, off);
    p += ptail;
    float inv = 1.f / (p + 1e-8f);
    if (lane == 0) g_sums[gw] = p;
    if (lane < kmain) g_att[beg + lane] = ex * inv;
    for (int k = 32 + lane; k < deg; k += 32)
        g_att[beg + k] = __expf(g_scores[beg + k] - mx) * inv;
}

// ---------------- pass 3 (chunked): weighted aggregation (R3 body) ----------------
__global__ void __launch_bounds__(256) k_agg(const float* __restrict__ messages,
                                             int n0, int n1) {
    int gw = n0 + ((blockIdx.x * blockDim.x + threadIdx.x) >> 5);
    int lane = threadIdx.x & 31;
    if (gw >= n1) return;
    int beg = g_offsets[gw], deg = g_offsets[gw + 1] - beg;
    const float4* m4 = (const float4*)messages;
    float4 acc = make_float4(0.f, 0.f, 0.f, 0.f);
    for (int k0 = 0; k0 < deg; k0 += 8) {
        int kb = deg - k0; if (kb > 8) kb = 8;
        int ee[8]; float ww[8]; float4 mm[8];
#pragma unroll
        for (int j = 0; j < 8; j++) if (j < kb) {
            ee[j] = __ldg(&g_eids[beg + k0 + j]);
            ww[j] = __ldg(&g_att[beg + k0 + j]);
        }
#pragma unroll
        for (int j = 0; j < 8; j++) if (j < kb) mm[j] = __ldg(m4 + (size_t)ee[j] * 32 + lane);
#pragma unroll
        for (int j = 0; j < 8; j++) if (j < kb) {
            acc.x = fmaf(ww[j], mm[j].x, acc.x);
            acc.y = fmaf(ww[j], mm[j].y, acc.y);
            acc.z = fmaf(ww[j], mm[j].z, acc.z);
            acc.w = fmaf(ww[j], mm[j].w, acc.w);
        }
    }
    ((float4*)g_wm)[(size_t)gw * 32 + lane] = acc;
}

// ---------------- output projection: out = wm @ Wvo + asum*bvo + bo (R3 verbatim) ------
__global__ void __launch_bounds__(128) k_out(const float* __restrict__ bo,
                                             float* __restrict__ out, int N) {
    const int TN = 16, P = 8;
    __shared__ __align__(16) float2 sp[P][D];
    __shared__ float sas[TN];
    int n0 = blockIdx.x * TN;
    int j = threadIdx.x;
#pragma unroll
    for (int p = 0; p < P; p++) {
        int na = n0 + 2 * p, nb = n0 + 2 * p + 1;
        if (na >= N) na = N - 1;
        if (nb >= N) nb = N - 1;
        sp[p][j] = make_float2(g_wm[(size_t)na * D + j], g_wm[(size_t)nb * D + j]);
    }
    if (j < TN) {
        int n = n0 + j; if (n >= N) n = N - 1;
        float s = g_sums[n];
        sas[j] = s / (s + 1e-8f);
    }
    __syncthreads();
    float bvoj = g_bvo[j];
    float boj  = __ldg(bo + j);
    unsigned long long acc[P];
#pragma unroll
    for (int p = 0; p < P; p++)
        acc[p] = pk2(fmaf(sas[2 * p], bvoj, boj), fmaf(sas[2 * p + 1], bvoj, boj));
#pragma unroll 4
    for (int i = 0; i < D; i++) {
        float w = __ldg(&g_Wvo[i * D + j]);
        unsigned long long bb = pk2(w, w);
#pragma unroll
        for (int p = 0; p < P; p++) {
            unsigned long long aa = *(const unsigned long long*)&sp[p][i];
            acc[p] = ffma2(aa, bb, acc[p]);
        }
    }
#pragma unroll
    for (int p = 0; p < P; p++) {
        float2 r = upk2(acc[p]);
        int na = n0 + 2 * p, nb = n0 + 2 * p + 1;
        if (na < N) out[(size_t)na * D + j] = r.x;
        if (nb < N) out[(size_t)nb * D + j] = r.y;
    }
}

// ---------------- launch ----------------
extern "C" void kernel_launch(void* const* d_in, const int* in_sizes, int n_in,
                              void* d_out, int out_size) {
    const float* messages = (const float*)d_in[0];
    const int*   recv     = (const int*)d_in[1];
    int wb = (n_in >= 11) ? 3 : 2;
    const float* Wk = (const float*)d_in[wb + 0];
    const float* bk = (const float*)d_in[wb + 1];
    const float* Wv = (const float*)d_in[wb + 2];
    const float* bv = (const float*)d_in[wb + 3];
    const float* Wq = (const float*)d_in[wb + 4];
    const float* bq = (const float*)d_in[wb + 5];
    const float* Wo = (const float*)d_in[wb + 6];
    const float* bo = (const float*)d_in[wb + 7];
    float* out = (float*)d_out;

    int E = in_sizes[0] / D;
    int N = out_size / D;
    int nb = (N + 255) / 256;

    // launch order chosen so ncu (-s 5 -c 1) captures k_sum_nodes (launch #6)
    k_init<<<(N + 255) / 256, 256>>>(N);                       // 1
    k_hist<<<(E + 255) / 256, 256>>>(recv, E);                 // 2
    k_scan1<<<nb, 256>>>(N);                                   // 3
    k_scan23<<<nb, 256>>>(N, E, nb);                           // 4
    k_scatter<<<(E + 255) / 256, 256>>>(recv, E);              // 5
    k_sum_nodes<<<(N + 7) / 8, 256>>>(messages, N);            // 6 <- profiled
    k_pre<<<D, D>>>(Wk, bk, Wv, bv, Wq, bq, Wo);               // 7
    k_qkproj<<<(N + 15) / 16, 128>>>(N);                       // 8

    // L2-chunked score/agg: each chunk's message rows (~82MB) stay L2-resident for agg
    const int NCHUNK = 4;
    int per = (N + NCHUNK - 1) / NCHUNK;
    for (int c = 0; c < NCHUNK; c++) {
        int c0 = c * per;
        int c1 = c0 + per; if (c1 > N) c1 = N;
        if (c0 >= c1) break;
        int nwarp = c1 - c0;
        k_score<<<(nwarp + 7) / 8, 256>>>(messages, c0, c1);
        k_agg  <<<(nwarp + 7) / 8, 256>>>(messages, c0, c1);
    }
    k_out<<<(N + 15) / 16, 128>>>(bo, out, N);
}